// round 4
// baseline (speedup 1.0000x reference)
#include <cuda_runtime.h>

#define NUM_B 2
#define NUM_H 32
#define SEQ   2048
#define HD    128
#define BM    128
#define BN    64
#define NTHREADS 256
#define KSTR  132   // K smem row stride (floats): conflict-free for K B-frag pattern
#define VSTR  136   // V smem row stride: conflict-free for V B-frag pattern
#define PSTR  76    // P smem row stride: conflict-free for P A-frag pattern
#define SMEM_FLOATS (2*BN*KSTR + 2*BN*VSTR + BM*PSTR)
#define SMEM_BYTES  (SMEM_FLOATS*4)

__device__ __forceinline__ unsigned f2tf(float x){
    unsigned r; asm("cvt.rna.tf32.f32 %0, %1;" : "=r"(r) : "f"(x)); return r;
}

__device__ __forceinline__ void mma_tf32(float c[4], const unsigned a[4],
                                         unsigned b0, unsigned b1){
    asm volatile("mma.sync.aligned.m16n8k8.row.col.f32.tf32.tf32.f32 "
                 "{%0,%1,%2,%3},{%4,%5,%6,%7},{%8,%9},{%0,%1,%2,%3};"
                 : "+f"(c[0]),"+f"(c[1]),"+f"(c[2]),"+f"(c[3])
                 : "r"(a[0]),"r"(a[1]),"r"(a[2]),"r"(a[3]),"r"(b0),"r"(b1));
}

__global__ void __launch_bounds__(NTHREADS, 1)
fa_fwd(const float* __restrict__ Q, const float* __restrict__ K,
       const float* __restrict__ V, float* __restrict__ Out)
{
    extern __shared__ float sm_[];
    float* Ks = sm_;
    float* Vs = sm_ + 2*BN*KSTR;
    float* Ps = sm_ + 2*BN*KSTR + 2*BN*VSTR;

    const int tid  = threadIdx.x;
    const int warp = tid >> 5;
    const int lane = tid & 31;
    const int r0   = lane >> 2;   // row-within-frag
    const int c0   = lane & 3;    // quad index

    const int qb = blockIdx.x, h = blockIdx.y, b = blockIdx.z;
    const int qbase = qb * BM;
    const size_t bh_off = ((size_t)b*NUM_H + h) * (size_t)SEQ * HD;
    const float* Qp = Q + bh_off;
    const float* Kp = K + bh_off;
    const float* Vp = V + bh_off;

    const unsigned ks_b = (unsigned)__cvta_generic_to_shared(Ks);
    const unsigned vs_b = (unsigned)__cvta_generic_to_shared(Vs);

    const float SCALE = 0.08838834764831845f;  // 1/sqrt(128): layer-scaling cancels

    // ---- Q fragments in registers, pre-scaled (64 regs, loaded once) ----
    unsigned qf[16][4];
    const int qrow0 = qbase + warp*16 + r0;
    const int qrow1 = qrow0 + 8;
    #pragma unroll
    for (int kt = 0; kt < 16; kt++){
        int col = kt*8 + c0;
        qf[kt][0] = f2tf(Qp[(size_t)qrow0*HD + col]     * SCALE);
        qf[kt][1] = f2tf(Qp[(size_t)qrow1*HD + col]     * SCALE);
        qf[kt][2] = f2tf(Qp[(size_t)qrow0*HD + col + 4] * SCALE);
        qf[kt][3] = f2tf(Qp[(size_t)qrow1*HD + col + 4] * SCALE);
    }

    // ---- Output accumulator (16 n-tiles x 4 regs = 64 regs) + softmax state ----
    float o[16][4];
    #pragma unroll
    for (int i = 0; i < 16; i++){ o[i][0]=0.f; o[i][1]=0.f; o[i][2]=0.f; o[i][3]=0.f; }
    float m0 = -1e30f, m1 = -1e30f, l0 = 0.f, l1 = 0.f;

    const int jmax = 2*qb + 1;   // causal: key blocks 0..jmax

    auto load_tiles = [&](int j, int buf){
        const float* kg = Kp + (size_t)j*BN*HD;
        const float* vg = Vp + (size_t)j*BN*HD;
        #pragma unroll
        for (int i = 0; i < (BN*HD/4)/NTHREADS; i++){   // 8 iters: 8 float4 / thread / tile
            int idx = tid + i*NTHREADS;
            int row = idx >> 5;
            int c4  = (idx & 31) * 4;
            unsigned ka = ks_b + (unsigned)((buf*BN*KSTR + row*KSTR + c4) * 4);
            unsigned va = vs_b + (unsigned)((buf*BN*VSTR + row*VSTR + c4) * 4);
            asm volatile("cp.async.cg.shared.global [%0], [%1], 16;"
                         :: "r"(ka), "l"(kg + (size_t)row*HD + c4));
            asm volatile("cp.async.cg.shared.global [%0], [%1], 16;"
                         :: "r"(va), "l"(vg + (size_t)row*HD + c4));
        }
        asm volatile("cp.async.commit_group;");
    };

    load_tiles(0, 0);

    for (int j = 0; j <= jmax; j++){
        const int cur = j & 1;
        if (j < jmax){
            load_tiles(j + 1, cur ^ 1);          // prefetch next into other buffer
            asm volatile("cp.async.wait_group 1;");
        } else {
            asm volatile("cp.async.wait_group 0;");
        }
        __syncthreads();

        const float* Kb = Ks + cur*BN*KSTR;
        const float* Vb = Vs + cur*BN*VSTR;

        // ---- S = Q * K^T  (warp computes 16x64) ----
        float sacc[8][4];
        #pragma unroll
        for (int i = 0; i < 8; i++){ sacc[i][0]=0.f; sacc[i][1]=0.f; sacc[i][2]=0.f; sacc[i][3]=0.f; }

        #pragma unroll
        for (int kt = 0; kt < 16; kt++){
            #pragma unroll
            for (int nt = 0; nt < 8; nt++){
                // B[k][n] = K[n][k]: b0 @ (k=c0, n=r0), b1 @ (k=c0+4, n=r0)
                const float* kb = &Kb[(nt*8 + r0)*KSTR + kt*8 + c0];
                unsigned b0 = f2tf(kb[0]);
                unsigned b1 = f2tf(kb[4]);
                mma_tf32(sacc[nt], qf[kt], b0, b1);
            }
        }

        // ---- causal mask (only the diagonal block pair needs it) ----
        const bool maskblk = (j*BN + BN) > qbase;
        float rmax0 = -1e30f, rmax1 = -1e30f;
        #pragma unroll
        for (int nt = 0; nt < 8; nt++){
            if (maskblk){
                int colb = j*BN + nt*8 + 2*c0;
                if (colb     > qrow0) sacc[nt][0] = -1e30f;
                if (colb + 1 > qrow0) sacc[nt][1] = -1e30f;
                if (colb     > qrow1) sacc[nt][2] = -1e30f;
                if (colb + 1 > qrow1) sacc[nt][3] = -1e30f;
            }
            rmax0 = fmaxf(rmax0, fmaxf(sacc[nt][0], sacc[nt][1]));
            rmax1 = fmaxf(rmax1, fmaxf(sacc[nt][2], sacc[nt][3]));
        }
        rmax0 = fmaxf(rmax0, __shfl_xor_sync(0xffffffffu, rmax0, 1));
        rmax0 = fmaxf(rmax0, __shfl_xor_sync(0xffffffffu, rmax0, 2));
        rmax1 = fmaxf(rmax1, __shfl_xor_sync(0xffffffffu, rmax1, 1));
        rmax1 = fmaxf(rmax1, __shfl_xor_sync(0xffffffffu, rmax1, 2));

        float m0n = fmaxf(m0, rmax0), m1n = fmaxf(m1, rmax1);
        float a0 = __expf(m0 - m0n), a1 = __expf(m1 - m1n);
        m0 = m0n; m1 = m1n;

        // ---- P = exp(S - m), row-sums, stash P to smem for re-fragmenting ----
        float* Pw = Ps + warp*16*PSTR;
        float rs0 = 0.f, rs1 = 0.f;
        #pragma unroll
        for (int nt = 0; nt < 8; nt++){
            float p0 = __expf(sacc[nt][0] - m0n);
            float p1 = __expf(sacc[nt][1] - m0n);
            float p2 = __expf(sacc[nt][2] - m1n);
            float p3 = __expf(sacc[nt][3] - m1n);
            rs0 += p0 + p1; rs1 += p2 + p3;
            *(float2*)&Pw[ r0     *PSTR + nt*8 + 2*c0] = make_float2(p0, p1);
            *(float2*)&Pw[(r0+8)  *PSTR + nt*8 + 2*c0] = make_float2(p2, p3);
        }
        rs0 += __shfl_xor_sync(0xffffffffu, rs0, 1);
        rs0 += __shfl_xor_sync(0xffffffffu, rs0, 2);
        rs1 += __shfl_xor_sync(0xffffffffu, rs1, 1);
        rs1 += __shfl_xor_sync(0xffffffffu, rs1, 2);
        l0 = l0*a0 + rs0;
        l1 = l1*a1 + rs1;

        #pragma unroll
        for (int nt = 0; nt < 16; nt++){
            o[nt][0] *= a0; o[nt][1] *= a0; o[nt][2] *= a1; o[nt][3] *= a1;
        }

        __syncwarp();   // P visible within warp (warp-private region)

        // ---- O += P * V ----
        unsigned pa[8][4];
        #pragma unroll
        for (int kt = 0; kt < 8; kt++){
            pa[kt][0] = f2tf(Pw[ r0    *PSTR + kt*8 + c0]);
            pa[kt][1] = f2tf(Pw[(r0+8) *PSTR + kt*8 + c0]);
            pa[kt][2] = f2tf(Pw[ r0    *PSTR + kt*8 + c0 + 4]);
            pa[kt][3] = f2tf(Pw[(r0+8) *PSTR + kt*8 + c0 + 4]);
        }
        #pragma unroll
        for (int kt = 0; kt < 8; kt++){
            #pragma unroll
            for (int nt = 0; nt < 16; nt++){
                // B[k][n] = V[k][n]: b0 @ (k=c0, n=r0), b1 @ (k=c0+4, n=r0)
                const float* vb = &Vb[(kt*8 + c0)*VSTR + nt*8 + r0];
                unsigned b0 = f2tf(vb[0]);
                unsigned b1 = f2tf(vb[4*VSTR]);
                mma_tf32(o[nt], pa[kt], b0, b1);
            }
        }
        __syncthreads();   // all done with this buffer before it's reloaded
    }

    // ---- epilogue: normalize + write [b, q, h*D] ----
    float inv0 = 1.f / l0, inv1 = 1.f / l1;
    const size_t ob = (size_t)b * SEQ * NUM_H * HD + (size_t)h * HD;
    #pragma unroll
    for (int nt = 0; nt < 16; nt++){
        int col = nt*8 + 2*c0;
        *(float2*)&Out[ob + (size_t)qrow0 * NUM_H * HD + col] =
            make_float2(o[nt][0]*inv0, o[nt][1]*inv0);
        *(float2*)&Out[ob + (size_t)qrow1 * NUM_H * HD + col] =
            make_float2(o[nt][2]*inv1, o[nt][3]*inv1);
    }
}

extern "C" void kernel_launch(void* const* d_in, const int* in_sizes, int n_in,
                              void* d_out, int out_size)
{
    const float* Q = (const float*)d_in[0];
    const float* K = (const float*)d_in[1];
    const float* V = (const float*)d_in[2];
    float* Out = (float*)d_out;

    cudaFuncSetAttribute(fa_fwd, cudaFuncAttributeMaxDynamicSharedMemorySize, SMEM_BYTES);

    dim3 grid(SEQ / BM, NUM_H, NUM_B);
    dim3 block(NTHREADS);
    fa_fwd<<<grid, block, SMEM_BYTES>>>(Q, K, V, Out);
}